// round 1
// baseline (speedup 1.0000x reference)
#include <cuda_runtime.h>
#include <math.h>

// JPEG round-trip, fused single kernel.
// Tile per CTA: 8 rows x 256 cols (= 32 8x8 blocks) x 3 channels.
// 256 threads: thread t -> (blk = t>>3, row = t&7). One thread owns one
// 8-element row/column of one block per pass. Shared stride 257 => all
// shared accesses are bank-conflict-free.

#define W 512
#define H 512
#define BATCH 32
#define TILE_W 256
#define SSTR 257          // shared stride (257 mod 32 == 1 -> conflict free)
#define PLANE (W * H)     // 262144

__constant__ float LUMc[64] = {
    16, 11, 10, 16, 24, 40, 51, 61,
    12, 12, 14, 19, 26, 58, 60, 55,
    14, 13, 16, 24, 40, 57, 69, 56,
    14, 17, 22, 29, 51, 87, 80, 62,
    18, 22, 37, 56, 68,109,103, 77,
    24, 35, 55, 64, 81,104,113, 92,
    49, 64, 78, 87,103,121,120,101,
    72, 92, 95, 98,112,100,103, 99 };
__constant__ float CHRc[64] = {
    17, 18, 24, 47, 99, 99, 99, 99,
    18, 21, 26, 66, 99, 99, 99, 99,
    24, 26, 56, 99, 99, 99, 99, 99,
    47, 66, 99, 99, 99, 99, 99, 99,
    99, 99, 99, 99, 99, 99, 99, 99,
    99, 99, 99, 99, 99, 99, 99, 99,
    99, 99, 99, 99, 99, 99, 99, 99,
    99, 99, 99, 99, 99, 99, 99, 99 };

__global__ __launch_bounds__(256) void jpeg_kernel(
    const float* __restrict__ in, const int* __restrict__ quality,
    float* __restrict__ out)
{
    __shared__ float sY[8 * SSTR];
    __shared__ float sCb[8 * SSTR];
    __shared__ float sCr[8 * SSTR];
    __shared__ float sScratch[8 * SSTR];
    __shared__ float sD[64];
    __shared__ float sQ[3 * 64];

    const int tid = threadIdx.x;

    // ---- build DCT matrix (matches numpy float64 -> float32 cast) ----
    if (tid < 64) {
        int i = tid >> 3, j = tid & 7;
        double v = cos((2.0 * j + 1.0) * i * M_PI / 16.0) * 0.5;
        if (i == 0) v *= 0.70710678118654752440;
        sD[tid] = (float)v;
    }
    // ---- build quant tables from quality scalar ----
    if (tid < 192) {
        int c = tid / 64, idx = tid % 64;
        int q = quality[0];
        q = max(1, min(100, q));
        double scale = (q < 50) ? (5000.0 / q) : (200.0 - 2.0 * q);
        double t = (double)((c == 0) ? LUMc[idx] : CHRc[idx]);
        double s = floor((t * scale + 50.0) / 100.0);
        s = fmin(fmax(s, 1.0), 255.0);
        sQ[tid] = (float)s;
    }

    // tile decomposition: 2 tiles in x, 64 block-rows, 32 batches
    const int tileIdx = blockIdx.x;
    const int tx = tileIdx & 1;
    const int rowblk = (tileIdx >> 1) & 63;
    const int batch = tileIdx >> 7;
    const int y0 = rowblk * 8;
    const int x0 = tx * TILE_W;

    const float* inB = in + (size_t)batch * 3 * PLANE;
    float* outB = out + (size_t)batch * 3 * PLANE;

    __syncthreads();

    // ---- load + RGB -> YCbCr (centered: -128 built in) ----
    #pragma unroll
    for (int i = tid; i < 8 * TILE_W; i += 256) {
        int yy = i >> 8, xx = i & 255;
        int g = (y0 + yy) * W + (x0 + xx);
        float r = rintf(fminf(fmaxf(inB[g], 0.f), 1.f) * 255.f);
        float gg = rintf(fminf(fmaxf(inB[g + PLANE], 0.f), 1.f) * 255.f);
        float b = rintf(fminf(fmaxf(inB[g + 2 * PLANE], 0.f), 1.f) * 255.f);
        float Y  = 0.299f * r + 0.587f * gg + 0.114f * b;
        float Cb = -0.168736f * r - 0.331264f * gg + 0.5f * b;      // +128-128
        float Cr = 0.5f * r - 0.418688f * gg - 0.081312f * b;       // +128-128
        int sa = yy * SSTR + xx;
        sY[sa] = Y - 128.f;
        sCb[sa] = Cb;
        sCr[sa] = Cr;
    }
    __syncthreads();

    const int blk = tid >> 3;   // 0..31
    const int row = tid & 7;    // 0..7
    const int cbase = blk * 8;

    float* chans[3] = { sY, sCb, sCr };

    #pragma unroll
    for (int c = 0; c < 3; c++) {
        float* ch = chans[c];
        const float* q = &sQ[c * 64];

        // ---- stage 1: row DCT.  B[row][i] = sum_j A[row][j]*D[i][j]
        // write transposed: scratch[i][blk*8+row] = B[row][i]
        {
            float a[8];
            #pragma unroll
            for (int j = 0; j < 8; j++) a[j] = ch[row * SSTR + cbase + j];
            #pragma unroll
            for (int i = 0; i < 8; i++) {
                float s = 0.f;
                #pragma unroll
                for (int j = 0; j < 8; j++) s = fmaf(sD[i * 8 + j], a[j], s);
                sScratch[i * SSTR + cbase + row] = s;
            }
        }
        __syncthreads();

        // ---- stage 2: column DCT + quantize + inverse column
        // thread handles column k = row of its block.
        {
            float a[8];
            #pragma unroll
            for (int r = 0; r < 8; r++) a[r] = sScratch[row * SSTR + cbase + r];
            float cc[8];
            #pragma unroll
            for (int i = 0; i < 8; i++) {
                float s = 0.f;
                #pragma unroll
                for (int r = 0; r < 8; r++) s = fmaf(sD[i * 8 + r], a[r], s);
                float qv = q[i * 8 + row];
                cc[i] = rintf(__fdiv_rn(s, qv)) * qv;
            }
            // E[j][k] = sum_i D[i][j]*C[i][k]
            #pragma unroll
            for (int j = 0; j < 8; j++) {
                float s = 0.f;
                #pragma unroll
                for (int i = 0; i < 8; i++) s = fmaf(sD[i * 8 + j], cc[i], s);
                ch[j * SSTR + cbase + row] = s;
            }
        }
        __syncthreads();

        // ---- stage 3: inverse row pass. rec[j][l] = sum_k E[j][k]*D[k][l]
        // thread owns row j = row of its block; read & write its own 8 slots.
        {
            float a[8];
            #pragma unroll
            for (int k = 0; k < 8; k++) a[k] = ch[row * SSTR + cbase + k];
            #pragma unroll
            for (int l = 0; l < 8; l++) {
                float s = 0.f;
                #pragma unroll
                for (int k = 0; k < 8; k++) s = fmaf(a[k], sD[k * 8 + l], s);
                ch[row * SSTR + cbase + l] = s;
            }
        }
        // no sync needed here: each thread touched only its own slots;
        // cross-thread visibility enforced by the sync below.
        __syncthreads();
    }

    // ---- YCbCr -> RGB, clip, round, /255, store ----
    #pragma unroll
    for (int i = tid; i < 8 * TILE_W; i += 256) {
        int yy = i >> 8, xx = i & 255;
        int sa = yy * SSTR + xx;
        float Y = sY[sa] + 128.f;
        float Cb = sCb[sa];
        float Cr = sCr[sa];
        float r = Y + 1.402f * Cr;
        float g = Y - 0.344136f * Cb - 0.714136f * Cr;
        float b = Y + 1.772f * Cb;
        int gidx = (y0 + yy) * W + (x0 + xx);
        outB[gidx] = __fdiv_rn(rintf(fminf(fmaxf(r, 0.f), 255.f)), 255.f);
        outB[gidx + PLANE] = __fdiv_rn(rintf(fminf(fmaxf(g, 0.f), 255.f)), 255.f);
        outB[gidx + 2 * PLANE] = __fdiv_rn(rintf(fminf(fmaxf(b, 0.f), 255.f)), 255.f);
    }
}

extern "C" void kernel_launch(void* const* d_in, const int* in_sizes, int n_in,
                              void* d_out, int out_size)
{
    // metadata order: input (float32, 32*3*512*512), quality (int32, 1)
    const float* in = (const float*)d_in[0];
    const int* quality = (const int*)d_in[1];
    if (n_in >= 2 && in_sizes[0] == 1) {  // defensive: swap if order reversed
        quality = (const int*)d_in[0];
        in = (const float*)d_in[1];
    }
    float* out = (float*)d_out;

    const int nCTA = BATCH * (H / 8) * (W / TILE_W);  // 32*64*2 = 4096
    jpeg_kernel<<<nCTA, 256>>>(in, quality, out);
}

// round 2
// speedup vs baseline: 2.2441x; 2.2441x over previous
#include <cuda_runtime.h>
#include <math.h>

#define W 512
#define H 512
#define PLANE (W * H)

// ---------------- compile-time DCT-II matrix (float32 of the float64 values) ----
// hcK = 0.5 * cos(K*pi/16)
#define HC1 0.4903926402016152f
#define HC2 0.4619397662556434f
#define HC3 0.4157348061512726f
#define HC4 0.3535533905932738f
#define HC5 0.2777851165098011f
#define HC6 0.1913417161825449f
#define HC7 0.0975451610080641f

__device__ static constexpr float DCT[8][8] = {
    { HC4,  HC4,  HC4,  HC4,  HC4,  HC4,  HC4,  HC4},
    { HC1,  HC3,  HC5,  HC7, -HC7, -HC5, -HC3, -HC1},
    { HC2,  HC6, -HC6, -HC2, -HC2, -HC6,  HC6,  HC2},
    { HC3, -HC7, -HC1, -HC5,  HC5,  HC1,  HC7, -HC3},
    { HC4, -HC4, -HC4,  HC4,  HC4, -HC4, -HC4,  HC4},
    { HC5, -HC1,  HC7,  HC3, -HC3, -HC7,  HC1, -HC5},
    { HC6, -HC2,  HC2, -HC6, -HC6,  HC2, -HC2,  HC6},
    { HC7, -HC5,  HC3, -HC1,  HC1, -HC3,  HC5, -HC7},
};

__constant__ float LUMc[64] = {
    16, 11, 10, 16, 24, 40, 51, 61,
    12, 12, 14, 19, 26, 58, 60, 55,
    14, 13, 16, 24, 40, 57, 69, 56,
    14, 17, 22, 29, 51, 87, 80, 62,
    18, 22, 37, 56, 68,109,103, 77,
    24, 35, 55, 64, 81,104,113, 92,
    49, 64, 78, 87,103,121,120,101,
    72, 92, 95, 98,112,100,103, 99 };
__constant__ float CHRc[64] = {
    17, 18, 24, 47, 99, 99, 99, 99,
    18, 21, 26, 66, 99, 99, 99, 99,
    24, 26, 56, 99, 99, 99, 99, 99,
    47, 66, 99, 99, 99, 99, 99, 99,
    99, 99, 99, 99, 99, 99, 99, 99,
    99, 99, 99, 99, 99, 99, 99, 99,
    99, 99, 99, 99, 99, 99, 99, 99,
    99, 99, 99, 99, 99, 99, 99, 99 };

// quant tables built once per launch by a tiny init kernel (double precision,
// matches the numpy reference bit-for-bit)
__device__ float gQ[192];

__global__ void init_q_kernel(const int* __restrict__ quality)
{
    int t = threadIdx.x;            // 0..191
    int c = t >> 6, idx = t & 63;
    int q = quality[0];
    q = max(1, min(100, q));
    double scale = (q < 50) ? (5000.0 / q) : (200.0 - 2.0 * q);
    double tv = (double)((c == 0) ? LUMc[idx] : CHRc[idx]);
    double s = floor((tv * scale + 50.0) / 100.0);
    s = fmin(fmax(s, 1.0), 255.0);
    gQ[t] = (float)s;
}

// 8x8 transpose across an 8-lane group (lanes l..l+7 of one warp), each lane
// holding one row in v[0..7]. Butterfly: element (r,c) -> (c,r).
__device__ __forceinline__ void transpose8(float v[8])
{
    #pragma unroll
    for (int m = 1; m < 8; m <<= 1) {
        bool hi = (threadIdx.x & m) != 0;
        #pragma unroll
        for (int a = 0; a < 8; a++) {
            if (a & m) continue;            // a = low index of pair
            int b = a | m;
            float t = hi ? v[a] : v[b];
            t = __shfl_xor_sync(0xFFFFFFFFu, t, m);
            if (hi) v[a] = t; else v[b] = t;
        }
    }
}

// Full per-block pipeline for one channel. On entry: lane (row r of the block)
// holds the centered spatial row in v[]. On exit: v[] holds the reconstructed
// (still centered) spatial row. k = this lane's index within its 8-lane group.
template<int C>
__device__ __forceinline__ void process_channel(float (&v)[8], int k)
{
    // row DCT: t[i] = sum_l D[i][l] * v[l]          (blk @ D^T, row-wise)
    float t[8];
    #pragma unroll
    for (int i = 0; i < 8; i++) {
        float s = 0.f;
        #pragma unroll
        for (int l = 0; l < 8; l++) s = fmaf(DCT[i][l], v[l], s);
        t[i] = s;
    }
    transpose8(t);                  // lane k now holds column k: t[j]

    // column DCT + quantize + inverse column
    float cc[8];
    #pragma unroll
    for (int i = 0; i < 8; i++) {
        float s = 0.f;
        #pragma unroll
        for (int j = 0; j < 8; j++) s = fmaf(DCT[i][j], t[j], s);
        float qv = __ldg(&gQ[C * 64 + i * 8 + k]);
        cc[i] = rintf(__fdiv_rn(s, qv)) * qv;
    }
    #pragma unroll
    for (int j = 0; j < 8; j++) {
        float s = 0.f;
        #pragma unroll
        for (int i = 0; i < 8; i++) s = fmaf(DCT[i][j], cc[i], s);
        t[j] = s;
    }
    transpose8(t);                  // lane j now holds row j of D^T*coef

    // inverse row pass: v[k'] = sum_l t[l] * D[l][k']
    #pragma unroll
    for (int kk = 0; kk < 8; kk++) {
        float s = 0.f;
        #pragma unroll
        for (int l = 0; l < 8; l++) s = fmaf(t[l], DCT[l][kk], s);
        v[kk] = s;
    }
}

__global__ void __launch_bounds__(256, 3) jpeg_kernel(
    const float* __restrict__ in, float* __restrict__ out)
{
    const int tid = threadIdx.x;
    const int blk = tid >> 3;       // 0..31  (8x8 block within the strip)
    const int row = tid & 7;        // 0..7   (row within the block; == group lane)

    // tile decomposition: 2 tiles in x, 64 block-rows, 32 batches
    const int tileIdx = blockIdx.x;
    const int tx = tileIdx & 1;
    const int rowblk = (tileIdx >> 1) & 63;
    const int batch = tileIdx >> 7;

    const size_t base = (size_t)batch * 3 * PLANE
                      + (size_t)(rowblk * 8 + row) * W
                      + tx * 256 + blk * 8;

    // ---- load 8 px of each plane (2x float4), RGB -> centered YCbCr ----
    const float4* pr = (const float4*)(in + base);
    const float4* pg = (const float4*)(in + base + PLANE);
    const float4* pb = (const float4*)(in + base + 2 * PLANE);
    float rv[8], gv[8], bv[8];
    *(float4*)&rv[0] = __ldg(pr);     *(float4*)&rv[4] = __ldg(pr + 1);
    *(float4*)&gv[0] = __ldg(pg);     *(float4*)&gv[4] = __ldg(pg + 1);
    *(float4*)&bv[0] = __ldg(pb);     *(float4*)&bv[4] = __ldg(pb + 1);

    float Y[8], Cb[8], Cr[8];
    #pragma unroll
    for (int e = 0; e < 8; e++) {
        float r = rintf(fminf(fmaxf(rv[e], 0.f), 1.f) * 255.f);
        float g = rintf(fminf(fmaxf(gv[e], 0.f), 1.f) * 255.f);
        float b = rintf(fminf(fmaxf(bv[e], 0.f), 1.f) * 255.f);
        Y[e]  = 0.299f * r + 0.587f * g + 0.114f * b - 128.f;
        Cb[e] = -0.168736f * r - 0.331264f * g + 0.5f * b;   // (+128 -128)
        Cr[e] = 0.5f * r - 0.418688f * g - 0.081312f * b;    // (+128 -128)
    }

    // ---- forward DCT -> quantize -> inverse DCT, per channel, all in regs ----
    process_channel<0>(Y,  row);
    process_channel<1>(Cb, row);
    process_channel<2>(Cr, row);

    // ---- YCbCr -> RGB, clip, round, /255, store (2x float4 per plane) ----
    const float inv255 = 1.0f / 255.0f;
    float R[8], G[8], B[8];
    #pragma unroll
    for (int e = 0; e < 8; e++) {
        float yy = Y[e] + 128.f;
        float cb = Cb[e];
        float cr = Cr[e];
        float r = yy + 1.402f * cr;
        float g = yy - 0.344136f * cb - 0.714136f * cr;
        float b = yy + 1.772f * cb;
        R[e] = rintf(fminf(fmaxf(r, 0.f), 255.f)) * inv255;
        G[e] = rintf(fminf(fmaxf(g, 0.f), 255.f)) * inv255;
        B[e] = rintf(fminf(fmaxf(b, 0.f), 255.f)) * inv255;
    }
    float4* qr = (float4*)(out + base);
    float4* qg = (float4*)(out + base + PLANE);
    float4* qb = (float4*)(out + base + 2 * PLANE);
    qr[0] = *(float4*)&R[0];  qr[1] = *(float4*)&R[4];
    qg[0] = *(float4*)&G[0];  qg[1] = *(float4*)&G[4];
    qb[0] = *(float4*)&B[0];  qb[1] = *(float4*)&B[4];
}

extern "C" void kernel_launch(void* const* d_in, const int* in_sizes, int n_in,
                              void* d_out, int out_size)
{
    const float* in = (const float*)d_in[0];
    const int* quality = (const int*)d_in[1];
    if (n_in >= 2 && in_sizes[0] == 1) {   // defensive: swap if order reversed
        quality = (const int*)d_in[0];
        in = (const float*)d_in[1];
    }
    float* out = (float*)d_out;

    init_q_kernel<<<1, 192>>>(quality);
    const int nCTA = 32 * 64 * 2;          // batches * block-rows * x-tiles
    jpeg_kernel<<<nCTA, 256>>>(in, out);
}

// round 3
// speedup vs baseline: 2.2944x; 1.0224x over previous
#include <cuda_runtime.h>
#include <math.h>

#define W 512
#define H 512
#define PLANE (W * H)

// hcK = 0.5 * cos(K*pi/16), float32 of the exact float64 values
#define HC1 0.4903926402016152f
#define HC2 0.4619397662556434f
#define HC3 0.4157348061512726f
#define HC4 0.3535533905932738f
#define HC5 0.2777851165098011f
#define HC6 0.1913417161825449f
#define HC7 0.0975451610080641f

__constant__ float LUMc[64] = {
    16, 11, 10, 16, 24, 40, 51, 61,
    12, 12, 14, 19, 26, 58, 60, 55,
    14, 13, 16, 24, 40, 57, 69, 56,
    14, 17, 22, 29, 51, 87, 80, 62,
    18, 22, 37, 56, 68,109,103, 77,
    24, 35, 55, 64, 81,104,113, 92,
    49, 64, 78, 87,103,121,120,101,
    72, 92, 95, 98,112,100,103, 99 };
__constant__ float CHRc[64] = {
    17, 18, 24, 47, 99, 99, 99, 99,
    18, 21, 26, 66, 99, 99, 99, 99,
    24, 26, 56, 99, 99, 99, 99, 99,
    47, 66, 99, 99, 99, 99, 99, 99,
    99, 99, 99, 99, 99, 99, 99, 99,
    99, 99, 99, 99, 99, 99, 99, 99,
    99, 99, 99, 99, 99, 99, 99, 99,
    99, 99, 99, 99, 99, 99, 99, 99 };

// [0..191] = q tables, [192..383] = reciprocals
__device__ float gQ[384];

__global__ void init_q_kernel(const int* __restrict__ quality)
{
    int t = threadIdx.x;            // 0..191
    int c = t >> 6, idx = t & 63;
    int q = quality[0];
    q = max(1, min(100, q));
    double scale = (q < 50) ? (5000.0 / q) : (200.0 - 2.0 * q);
    double tv = (double)((c == 0) ? LUMc[idx] : CHRc[idx]);
    double s = floor((tv * scale + 50.0) / 100.0);
    s = fmin(fmax(s, 1.0), 255.0);
    gQ[t] = (float)s;
    gQ[192 + t] = (float)(1.0 / s);
}

// forward 8-pt DCT-II (even/odd factored): c[i] = sum_l D[i][l] v[l]
__device__ __forceinline__ void fwd8(const float v[8], float c[8])
{
    float e0 = v[0] + v[7], e1 = v[1] + v[6], e2 = v[2] + v[5], e3 = v[3] + v[4];
    float o0 = v[0] - v[7], o1 = v[1] - v[6], o2 = v[2] - v[5], o3 = v[3] - v[4];
    c[0] = fmaf(HC4,e0, fmaf(HC4,e1, fmaf(HC4,e2, HC4*e3)));
    c[2] = fmaf(HC2,e0, fmaf(HC6,e1, fmaf(-HC6,e2, -HC2*e3)));
    c[4] = fmaf(HC4,e0, fmaf(-HC4,e1, fmaf(-HC4,e2, HC4*e3)));
    c[6] = fmaf(HC6,e0, fmaf(-HC2,e1, fmaf(HC2,e2, -HC6*e3)));
    c[1] = fmaf(HC1,o0, fmaf(HC3,o1, fmaf(HC5,o2, HC7*o3)));
    c[3] = fmaf(HC3,o0, fmaf(-HC7,o1, fmaf(-HC1,o2, -HC5*o3)));
    c[5] = fmaf(HC5,o0, fmaf(-HC1,o1, fmaf(HC7,o2, HC3*o3)));
    c[7] = fmaf(HC7,o0, fmaf(-HC5,o1, fmaf(HC3,o2, -HC1*o3)));
}

// inverse pass: out[j] = sum_i D[i][j] c[i]  (apply D^T)
__device__ __forceinline__ void inv8(const float c[8], float out[8])
{
    float p0 = fmaf(HC4,c[0], fmaf(HC2,c[2], fmaf(HC4,c[4], HC6*c[6])));
    float p1 = fmaf(HC4,c[0], fmaf(HC6,c[2], fmaf(-HC4,c[4], -HC2*c[6])));
    float p2 = fmaf(HC4,c[0], fmaf(-HC6,c[2], fmaf(-HC4,c[4], HC2*c[6])));
    float p3 = fmaf(HC4,c[0], fmaf(-HC2,c[2], fmaf(HC4,c[4], -HC6*c[6])));
    float m0 = fmaf(HC1,c[1], fmaf(HC3,c[3], fmaf(HC5,c[5], HC7*c[7])));
    float m1 = fmaf(HC3,c[1], fmaf(-HC7,c[3], fmaf(-HC1,c[5], -HC5*c[7])));
    float m2 = fmaf(HC5,c[1], fmaf(-HC1,c[3], fmaf(HC7,c[5], HC3*c[7])));
    float m3 = fmaf(HC7,c[1], fmaf(-HC5,c[3], fmaf(HC3,c[5], -HC1*c[7])));
    out[0] = p0 + m0;  out[7] = p0 - m0;
    out[1] = p1 + m1;  out[6] = p1 - m1;
    out[2] = p2 + m2;  out[5] = p2 - m2;
    out[3] = p3 + m3;  out[4] = p3 - m3;
}

// Shared transpose scratch: per warp, per group: 8 rows x pad-12, group stride 104.
//  - write (STS.128 x2 at row stride 12): conflict-free per 8-lane phase
//  - read column r (8x LDS.32): banks (8g + 12i + r) mod 32 distinct per iter
#define GSTR 104
#define RSTR 12
#define WARP_BUF (4 * GSTR)     // 416 floats per warp per buffer

// transpose 8x8 within an 8-lane group through smem buffer `buf` (per-warp base).
// in: t[0..7] = this lane's row r. out: t[0..7] = this lane's column r.
__device__ __forceinline__ void transpose8s(float t[8], float* buf, int g, int r)
{
    float* wr = buf + g * GSTR + r * RSTR;
    *(float4*)wr       = *(float4*)&t[0];
    *(float4*)(wr + 4) = *(float4*)&t[4];
    __syncwarp();
    const float* rd = buf + g * GSTR + r;
    #pragma unroll
    for (int i = 0; i < 8; i++) t[i] = rd[i * RSTR];
}

template<int C>
__device__ __forceinline__ void process_channel(float (&v)[8], float* bufA,
                                                float* bufB, int g, int r)
{
    float t[8];
    fwd8(v, t);                    // row DCT
    transpose8s(t, bufA, g, r);    // now t = column r of row-DCT result
    float c[8];
    fwd8(t, c);                    // column DCT -> full coeffs, column r
    // quantize/dequantize: round(s/q)*q via hoisted reciprocal + 1 Newton step
    #pragma unroll
    for (int i = 0; i < 8; i++) {
        float qv = __ldg(&gQ[C * 64 + i * 8 + r]);
        float rq = __ldg(&gQ[192 + C * 64 + i * 8 + r]);
        float y0 = c[i] * rq;
        float y1 = fmaf(fmaf(-qv, y0, c[i]), rq, y0);
        c[i] = rintf(y1) * qv;
    }
    inv8(c, t);                    // column IDCT
    transpose8s(t, bufB, g, r);    // back to rows
    inv8(t, v);                    // row IDCT
}

__global__ void __launch_bounds__(256, 5) jpeg_kernel(
    const float* __restrict__ in, float* __restrict__ out)
{
    __shared__ float smemA[8][WARP_BUF];
    __shared__ float smemB[8][WARP_BUF];

    const int tid = threadIdx.x;
    const int w = tid >> 5;         // warp 0..7
    const int g = (tid >> 3) & 3;   // 8-lane group within warp
    const int r = tid & 7;          // row within 8x8 block
    const int blk = tid >> 3;       // 0..31 (block within strip)

    float* bufA = smemA[w];
    float* bufB = smemB[w];

    const int tileIdx = blockIdx.x;
    const int tx = tileIdx & 1;
    const int rowblk = (tileIdx >> 1) & 63;
    const int batch = tileIdx >> 7;

    const size_t base = (size_t)batch * 3 * PLANE
                      + (size_t)(rowblk * 8 + r) * W
                      + tx * 256 + blk * 8;

    const float4* pr = (const float4*)(in + base);
    const float4* pg = (const float4*)(in + base + PLANE);
    const float4* pb = (const float4*)(in + base + 2 * PLANE);
    float rv[8], gv[8], bv[8];
    *(float4*)&rv[0] = __ldg(pr);   *(float4*)&rv[4] = __ldg(pr + 1);
    *(float4*)&gv[0] = __ldg(pg);   *(float4*)&gv[4] = __ldg(pg + 1);
    *(float4*)&bv[0] = __ldg(pb);   *(float4*)&bv[4] = __ldg(pb + 1);

    float Y[8], Cb[8], Cr[8];
    #pragma unroll
    for (int e = 0; e < 8; e++) {
        float rr = rintf(fminf(fmaxf(rv[e], 0.f), 1.f) * 255.f);
        float gg = rintf(fminf(fmaxf(gv[e], 0.f), 1.f) * 255.f);
        float bb = rintf(fminf(fmaxf(bv[e], 0.f), 1.f) * 255.f);
        Y[e]  = 0.299f * rr + 0.587f * gg + 0.114f * bb - 128.f;
        Cb[e] = -0.168736f * rr - 0.331264f * gg + 0.5f * bb;   // (+128 -128)
        Cr[e] = 0.5f * rr - 0.418688f * gg - 0.081312f * bb;    // (+128 -128)
    }

    process_channel<0>(Y,  bufA, bufB, g, r);
    process_channel<1>(Cb, bufA, bufB, g, r);
    process_channel<2>(Cr, bufA, bufB, g, r);

    const float inv255 = 1.0f / 255.0f;
    float R[8], G[8], B[8];
    #pragma unroll
    for (int e = 0; e < 8; e++) {
        float yy = Y[e] + 128.f;
        float cb = Cb[e];
        float cr = Cr[e];
        float rr = yy + 1.402f * cr;
        float gg = yy - 0.344136f * cb - 0.714136f * cr;
        float bb = yy + 1.772f * cb;
        R[e] = rintf(fminf(fmaxf(rr, 0.f), 255.f)) * inv255;
        G[e] = rintf(fminf(fmaxf(gg, 0.f), 255.f)) * inv255;
        B[e] = rintf(fminf(fmaxf(bb, 0.f), 255.f)) * inv255;
    }
    float4* qr = (float4*)(out + base);
    float4* qg = (float4*)(out + base + PLANE);
    float4* qb = (float4*)(out + base + 2 * PLANE);
    qr[0] = *(float4*)&R[0];  qr[1] = *(float4*)&R[4];
    qg[0] = *(float4*)&G[0];  qg[1] = *(float4*)&G[4];
    qb[0] = *(float4*)&B[0];  qb[1] = *(float4*)&B[4];
}

extern "C" void kernel_launch(void* const* d_in, const int* in_sizes, int n_in,
                              void* d_out, int out_size)
{
    const float* in = (const float*)d_in[0];
    const int* quality = (const int*)d_in[1];
    if (n_in >= 2 && in_sizes[0] == 1) {   // defensive: swap if order reversed
        quality = (const int*)d_in[0];
        in = (const float*)d_in[1];
    }
    float* out = (float*)d_out;

    init_q_kernel<<<1, 192>>>(quality);
    const int nCTA = 32 * 64 * 2;          // batches * block-rows * x-tiles
    jpeg_kernel<<<nCTA, 256>>>(in, out);
}

// round 4
// speedup vs baseline: 2.3019x; 1.0033x over previous
#include <cuda_runtime.h>
#include <math.h>

#define W 512
#define H 512
#define PLANE (W * H)

// hcK = 0.5 * cos(K*pi/16), float32 of the exact float64 values
#define HC1 0.4903926402016152f
#define HC2 0.4619397662556434f
#define HC3 0.4157348061512726f
#define HC4 0.3535533905932738f
#define HC5 0.2777851165098011f
#define HC6 0.1913417161825449f
#define HC7 0.0975451610080641f

__constant__ float LUMc[64] = {
    16, 11, 10, 16, 24, 40, 51, 61,
    12, 12, 14, 19, 26, 58, 60, 55,
    14, 13, 16, 24, 40, 57, 69, 56,
    14, 17, 22, 29, 51, 87, 80, 62,
    18, 22, 37, 56, 68,109,103, 77,
    24, 35, 55, 64, 81,104,113, 92,
    49, 64, 78, 87,103,121,120,101,
    72, 92, 95, 98,112,100,103, 99 };
__constant__ float CHRc[64] = {
    17, 18, 24, 47, 99, 99, 99, 99,
    18, 21, 26, 66, 99, 99, 99, 99,
    24, 26, 56, 99, 99, 99, 99, 99,
    47, 66, 99, 99, 99, 99, 99, 99,
    99, 99, 99, 99, 99, 99, 99, 99,
    99, 99, 99, 99, 99, 99, 99, 99,
    99, 99, 99, 99, 99, 99, 99, 99,
    99, 99, 99, 99, 99, 99, 99, 99 };

// forward 8-pt DCT-II (even/odd factored): c[i] = sum_l D[i][l] v[l]
__device__ __forceinline__ void fwd8(const float v[8], float c[8])
{
    float e0 = v[0] + v[7], e1 = v[1] + v[6], e2 = v[2] + v[5], e3 = v[3] + v[4];
    float o0 = v[0] - v[7], o1 = v[1] - v[6], o2 = v[2] - v[5], o3 = v[3] - v[4];
    c[0] = fmaf(HC4,e0, fmaf(HC4,e1, fmaf(HC4,e2, HC4*e3)));
    c[2] = fmaf(HC2,e0, fmaf(HC6,e1, fmaf(-HC6,e2, -HC2*e3)));
    c[4] = fmaf(HC4,e0, fmaf(-HC4,e1, fmaf(-HC4,e2, HC4*e3)));
    c[6] = fmaf(HC6,e0, fmaf(-HC2,e1, fmaf(HC2,e2, -HC6*e3)));
    c[1] = fmaf(HC1,o0, fmaf(HC3,o1, fmaf(HC5,o2, HC7*o3)));
    c[3] = fmaf(HC3,o0, fmaf(-HC7,o1, fmaf(-HC1,o2, -HC5*o3)));
    c[5] = fmaf(HC5,o0, fmaf(-HC1,o1, fmaf(HC7,o2, HC3*o3)));
    c[7] = fmaf(HC7,o0, fmaf(-HC5,o1, fmaf(HC3,o2, -HC1*o3)));
}

// inverse pass: out[j] = sum_i D[i][j] c[i]  (apply D^T)
__device__ __forceinline__ void inv8(const float c[8], float out[8])
{
    float p0 = fmaf(HC4,c[0], fmaf(HC2,c[2], fmaf(HC4,c[4], HC6*c[6])));
    float p1 = fmaf(HC4,c[0], fmaf(HC6,c[2], fmaf(-HC4,c[4], -HC2*c[6])));
    float p2 = fmaf(HC4,c[0], fmaf(-HC6,c[2], fmaf(-HC4,c[4], HC2*c[6])));
    float p3 = fmaf(HC4,c[0], fmaf(-HC2,c[2], fmaf(HC4,c[4], -HC6*c[6])));
    float m0 = fmaf(HC1,c[1], fmaf(HC3,c[3], fmaf(HC5,c[5], HC7*c[7])));
    float m1 = fmaf(HC3,c[1], fmaf(-HC7,c[3], fmaf(-HC1,c[5], -HC5*c[7])));
    float m2 = fmaf(HC5,c[1], fmaf(-HC1,c[3], fmaf(HC7,c[5], HC3*c[7])));
    float m3 = fmaf(HC7,c[1], fmaf(-HC5,c[3], fmaf(HC3,c[5], -HC1*c[7])));
    out[0] = p0 + m0;  out[7] = p0 - m0;
    out[1] = p1 + m1;  out[6] = p1 - m1;
    out[2] = p2 + m2;  out[5] = p2 - m2;
    out[3] = p3 + m3;  out[4] = p3 - m3;
}

// Per-warp transpose scratch, per 8-lane group: 8 rows x stride-12, group stride 104.
//  writes (2x STS.128 at row stride 12) and strided column reads are conflict-free.
#define GSTR 104
#define RSTR 12
#define WARP_BUF (4 * GSTR)     // 416 floats per warp per channel buffer

__global__ void __launch_bounds__(256, 4) jpeg_kernel(
    const float* __restrict__ in, const int* __restrict__ quality,
    float* __restrict__ out)
{
    __shared__ float bufs[3][8][WARP_BUF];   // [channel][warp][scratch]  ~39.9KB
    __shared__ float qsm[192];               // transposed q:  [c][r][i]
    __shared__ float rqsm[192];              // reciprocals, same layout

    const int tid = threadIdx.x;
    const int w = tid >> 5;         // warp 0..7
    const int g = (tid >> 3) & 3;   // 8-lane group within warp
    const int r = tid & 7;          // row within 8x8 block
    const int blk = tid >> 3;       // 0..31 (block within strip)

    // ---- build transposed quant tables (q + 1/q) in shared, double precision ----
    if (tid < 192) {
        int c = tid >> 6;
        int rr = (tid >> 3) & 7;    // output column index
        int ii = tid & 7;           // output row index -> table entry (ii, rr)
        int q = quality[0];
        q = max(1, min(100, q));
        double scale = (q < 50) ? (5000.0 / q) : (200.0 - 2.0 * q);
        double tv = (double)((c == 0) ? LUMc[ii * 8 + rr] : CHRc[ii * 8 + rr]);
        double s = floor((tv * scale + 50.0) / 100.0);
        s = fmin(fmax(s, 1.0), 255.0);
        qsm[tid] = (float)s;
        rqsm[tid] = (float)(1.0 / s);
    }

    const int tileIdx = blockIdx.x;
    const int tx = tileIdx & 1;
    const int rowblk = (tileIdx >> 1) & 63;
    const int batch = tileIdx >> 7;

    const size_t base = (size_t)batch * 3 * PLANE
                      + (size_t)(rowblk * 8 + r) * W
                      + tx * 256 + blk * 8;

    // ---- load + color convert ----
    const float4* pr = (const float4*)(in + base);
    const float4* pg = (const float4*)(in + base + PLANE);
    const float4* pb = (const float4*)(in + base + 2 * PLANE);
    float rv[8], gv[8], bv[8];
    *(float4*)&rv[0] = __ldg(pr);   *(float4*)&rv[4] = __ldg(pr + 1);
    *(float4*)&gv[0] = __ldg(pg);   *(float4*)&gv[4] = __ldg(pg + 1);
    *(float4*)&bv[0] = __ldg(pb);   *(float4*)&bv[4] = __ldg(pb + 1);

    float ch[3][8];                 // Y, Cb, Cr rows (centered)
    #pragma unroll
    for (int e = 0; e < 8; e++) {
        float rr = rintf(__saturatef(rv[e]) * 255.f);
        float gg = rintf(__saturatef(gv[e]) * 255.f);
        float bb = rintf(__saturatef(bv[e]) * 255.f);
        ch[0][e] = 0.299f * rr + 0.587f * gg + 0.114f * bb - 128.f;
        ch[1][e] = -0.168736f * rr - 0.331264f * gg + 0.5f * bb;   // (+128 -128)
        ch[2][e] = 0.5f * rr - 0.418688f * gg - 0.081312f * bb;    // (+128 -128)
    }

    float* wbase0 = &bufs[0][w][g * GSTR + r * RSTR];
    float* wbase1 = &bufs[1][w][g * GSTR + r * RSTR];
    float* wbase2 = &bufs[2][w][g * GSTR + r * RSTR];
    const float* rbase0 = &bufs[0][w][g * GSTR + r];
    const float* rbase1 = &bufs[1][w][g * GSTR + r];
    const float* rbase2 = &bufs[2][w][g * GSTR + r];

    // ---- phase 1: row DCT for all 3 channels, write rows ----
    #pragma unroll
    for (int c = 0; c < 3; c++) {
        float t[8];
        fwd8(ch[c], t);
        float* wr = (c == 0) ? wbase0 : (c == 1) ? wbase1 : wbase2;
        *(float4*)wr       = *(float4*)&t[0];
        *(float4*)(wr + 4) = *(float4*)&t[4];
    }
    __syncwarp();

    // ---- phase 2: batched column reads (24 independent LDS) ----
    float tc[3][8];
    #pragma unroll
    for (int i = 0; i < 8; i++) tc[0][i] = rbase0[i * RSTR];
    #pragma unroll
    for (int i = 0; i < 8; i++) tc[1][i] = rbase1[i * RSTR];
    #pragma unroll
    for (int i = 0; i < 8; i++) tc[2][i] = rbase2[i * RSTR];
    __syncthreads();   // (a) reads done before buffer reuse  (b) q tables published

    // ---- phase 3: column DCT + quantize + column IDCT, write rows (reuse bufs) ----
    #pragma unroll
    for (int c = 0; c < 3; c++) {
        float cc[8];
        fwd8(tc[c], cc);
        const float4* qp  = (const float4*)&qsm[c * 64 + r * 8];
        const float4* rqp = (const float4*)&rqsm[c * 64 + r * 8];
        float4 q03 = qp[0],  q47 = qp[1];
        float4 r03 = rqp[0], r47 = rqp[1];
        const float* qv = (const float*)&q03;   // q03,q47 contiguous? use explicit
        float qa[8] = { q03.x, q03.y, q03.z, q03.w, q47.x, q47.y, q47.z, q47.w };
        float ra[8] = { r03.x, r03.y, r03.z, r03.w, r47.x, r47.y, r47.z, r47.w };
        (void)qv;
        #pragma unroll
        for (int i = 0; i < 8; i++) {
            float y0 = cc[i] * ra[i];
            float y1 = fmaf(fmaf(-qa[i], y0, cc[i]), ra[i], y0);
            cc[i] = rintf(y1) * qa[i];
        }
        float t[8];
        inv8(cc, t);
        float* wr = (c == 0) ? wbase0 : (c == 1) ? wbase1 : wbase2;
        *(float4*)wr       = *(float4*)&t[0];
        *(float4*)(wr + 4) = *(float4*)&t[4];
    }
    __syncwarp();

    // ---- phase 4: batched column reads again ----
    #pragma unroll
    for (int i = 0; i < 8; i++) tc[0][i] = rbase0[i * RSTR];
    #pragma unroll
    for (int i = 0; i < 8; i++) tc[1][i] = rbase1[i * RSTR];
    #pragma unroll
    for (int i = 0; i < 8; i++) tc[2][i] = rbase2[i * RSTR];

    // ---- phase 5: row IDCT + color back-convert + store ----
    #pragma unroll
    for (int c = 0; c < 3; c++) inv8(tc[c], ch[c]);

    const float inv255 = 1.0f / 255.0f;
    float R[8], G[8], B[8];
    #pragma unroll
    for (int e = 0; e < 8; e++) {
        float yy = ch[0][e] + 128.f;
        float cb = ch[1][e];
        float cr = ch[2][e];
        float rr = yy + 1.402f * cr;
        float gg = yy - 0.344136f * cb - 0.714136f * cr;
        float bb = yy + 1.772f * cb;
        R[e] = rintf(fminf(fmaxf(rr, 0.f), 255.f)) * inv255;
        G[e] = rintf(fminf(fmaxf(gg, 0.f), 255.f)) * inv255;
        B[e] = rintf(fminf(fmaxf(bb, 0.f), 255.f)) * inv255;
    }
    float4* qr = (float4*)(out + base);
    float4* qg = (float4*)(out + base + PLANE);
    float4* qb = (float4*)(out + base + 2 * PLANE);
    qr[0] = *(float4*)&R[0];  qr[1] = *(float4*)&R[4];
    qg[0] = *(float4*)&G[0];  qg[1] = *(float4*)&G[4];
    qb[0] = *(float4*)&B[0];  qb[1] = *(float4*)&B[4];
}

extern "C" void kernel_launch(void* const* d_in, const int* in_sizes, int n_in,
                              void* d_out, int out_size)
{
    const float* in = (const float*)d_in[0];
    const int* quality = (const int*)d_in[1];
    if (n_in >= 2 && in_sizes[0] == 1) {   // defensive: swap if order reversed
        quality = (const int*)d_in[0];
        in = (const float*)d_in[1];
    }
    float* out = (float*)d_out;

    const int nCTA = 32 * 64 * 2;          // batches * block-rows * x-tiles
    jpeg_kernel<<<nCTA, 256>>>(in, quality, out);
}